// round 14
// baseline (speedup 1.0000x reference)
#include <cuda_runtime.h>
#include <cuda_bf16.h>
#include <math.h>
#include <stdint.h>

#define BATCH   256
#define LATENT  64
#define HID     256
#define GATES   1024
#define OUTD    128
#define SEQ     512
#define CHUNK   128

#define CLUSTER   8
#define NCLUSTER  16
#define ROWS      16
#define JLOC      32
#define NTH       512

// ---- dynamic smem layout (bytes) ----
#define ROWSTR   528
#define BUF_LO   8448
#define BUFSZ    16896
#define GXSZ     9216                     // 128*18*4
#define OFF_SB    0                       // 3 buffers
#define OFF_STAGE (3 * BUFSZ)             // 50688: hi 1024 + lo 1024
#define OFF_XP    (OFF_STAGE + 2048)      // 52736: float[16][132]
#define OFF_GX    (OFF_XP + 8448)         // 61184: 2 x float[128][18]
#define OFF_MBAR  (OFF_GX + 2 * GXSZ)     // 79616
#define SMEM_LSTM (OFF_MBAR + 64)         // 79680

// ---------------- persistent device scratch ----------------
__device__ float g_wT_ih[HID * GATES];
__device__ float g_fcwT [LATENT * HID];
__device__ float g_outT [HID * OUTD];
__device__ float g_h0   [BATCH * HID];
__device__ float g_c    [BATCH * HID];
__device__ float g_xproj[BATCH * GATES];
__device__ float g_hs   [SEQ * BATCH * HID];
__device__ __nv_bfloat16 g_whi[CLUSTER * 128 * 256];   // per-rank [nl][k]
__device__ __nv_bfloat16 g_wlo[CLUSTER * 128 * 256];

// ---------------- helpers ----------------
__device__ __forceinline__ void fma2(unsigned long long& d, unsigned long long a,
                                     unsigned long long b) {
    asm("fma.rn.f32x2 %0, %1, %2, %0;" : "+l"(d) : "l"(a), "l"(b));
}
__device__ __forceinline__ float2 upk2(unsigned long long v) {
    float2 r;
    asm("mov.b64 {%0, %1}, %2;" : "=f"(r.x), "=f"(r.y) : "l"(v));
    return r;
}
__device__ __forceinline__ float sigmoid_x(float x) {
    return __frcp_rn(1.f + __expf(-x));
}
__device__ __forceinline__ float tanh_x(float x) {
    return 1.f - 2.f * __frcp_rn(1.f + __expf(2.f * x));
}
__device__ __forceinline__ uint32_t smem_u32(const void* p) {
    uint32_t a;
    asm("{ .reg .u64 t; cvta.to.shared.u64 t, %1; cvt.u32.u64 %0, t; }" : "=r"(a) : "l"(p));
    return a;
}
__device__ __forceinline__ uint32_t mapa_u32(uint32_t addr, uint32_t rank) {
    uint32_t r;
    asm("mapa.shared::cluster.u32 %0, %1, %2;" : "=r"(r) : "r"(addr), "r"(rank));
    return r;
}
__device__ __forceinline__ void mma_bf16(float d[4], const uint32_t a[4],
                                         uint32_t b0, uint32_t b1) {
    asm volatile(
        "mma.sync.aligned.m16n8k16.row.col.f32.bf16.bf16.f32 "
        "{%0,%1,%2,%3}, {%4,%5,%6,%7}, {%8,%9}, {%0,%1,%2,%3};"
        : "+f"(d[0]), "+f"(d[1]), "+f"(d[2]), "+f"(d[3])
        : "r"(a[0]), "r"(a[1]), "r"(a[2]), "r"(a[3]), "r"(b0), "r"(b1));
}
// consumer wait: acquire at CLUSTER scope (pairs with producers' release arrives)
__device__ __forceinline__ void mbar_wait_cluster(uint32_t mbar, uint32_t parity) {
    asm volatile("{\n\t.reg .pred P1;\n\t"
                 "WAIT_LOOP_%=:\n\t"
                 "mbarrier.try_wait.parity.acquire.cluster.shared::cta.b64 P1, [%0], %1, 0x989680;\n\t"
                 "@P1 bra.uni WAIT_DONE_%=;\n\t"
                 "bra.uni WAIT_LOOP_%=;\n\t"
                 "WAIT_DONE_%=:\n\t}" :: "r"(mbar), "r"(parity) : "memory");
}

// ---------------- prep: W split (bf16 hi/lo) + transposes ----------------
__device__ __forceinline__ void do_transpose(const float* __restrict__ src,
                                             float* __restrict__ dst,
                                             int R, int C, int bx, int by, int tid) {
    __shared__ float tile[32][33];
    int tx = tid & 31;
    int ty = tid >> 5;
#pragma unroll
    for (int p = 0; p < 32; p += 8) {
        int r = by * 32 + ty + p, c = bx * 32 + tx;
        if (r < R && c < C) tile[ty + p][tx] = src[r * C + c];
    }
    __syncthreads();
#pragma unroll
    for (int p = 0; p < 32; p += 8) {
        int r = by * 32 + tx, c = bx * 32 + ty + p;
        if (r < R && c < C) dst[c * R + r] = tile[tx][ty + p];
    }
}

__global__ void prep_kernel(const float* __restrict__ w_hh, const float* __restrict__ w_ih,
                            const float* __restrict__ fc_w, const float* __restrict__ out_w) {
    int b = blockIdx.x;
    int tid = threadIdx.x;
    if (b < 256) {
        int rank = b >> 5, rg = b & 31;
        int k = tid;
#pragma unroll
        for (int q = 0; q < 4; q++) {
            int nl = rg * 4 + q;
            int g = nl >> 5, jj = nl & 31;
            float w = w_hh[(g * 256 + rank * JLOC + jj) * HID + k];
            __nv_bfloat16 hi = __float2bfloat16(w);
            __nv_bfloat16 lo = __float2bfloat16(w - __bfloat162float(hi));
            uint32_t idx = rank * 32768 + nl * 256 + k;
            g_whi[idx] = hi;
            g_wlo[idx] = lo;
        }
    } else if (b < 512) {
        int t = b - 256;
        do_transpose(w_ih, g_wT_ih, GATES, HID, t & 7, t >> 3, tid);
    } else if (b < 528) {
        int t = b - 512;
        do_transpose(fc_w, g_fcwT, HID, LATENT, t & 1, t >> 1, tid);
    } else {
        int t = b - 528;
        do_transpose(out_w, g_outT, OUTD, HID, t & 7, t >> 3, tid);
    }
}

// ---------------- h0 = z @ fc_w^T + fc_b ----------------
__global__ void h0_kernel(const float* __restrict__ z, const float* __restrict__ fc_b) {
    __shared__ float sh_z[4][LATENT];
    int tid = threadIdx.x;
    int b0 = blockIdx.x * 4;
    {
        int row = tid >> 6, k = tid & 63;
        sh_z[row][k] = z[(b0 + row) * LATENT + k];
    }
    __syncthreads();
    float acc0 = 0.f, acc1 = 0.f, acc2 = 0.f, acc3 = 0.f;
    int j = tid;
#pragma unroll 8
    for (int k = 0; k < LATENT; k++) {
        float w = g_fcwT[k * HID + j];
        acc0 = fmaf(sh_z[0][k], w, acc0);
        acc1 = fmaf(sh_z[1][k], w, acc1);
        acc2 = fmaf(sh_z[2][k], w, acc2);
        acc3 = fmaf(sh_z[3][k], w, acc3);
    }
    float bb = fc_b[j];
    g_h0[(b0 + 0) * HID + j] = acc0 + bb;
    g_h0[(b0 + 1) * HID + j] = acc1 + bb;
    g_h0[(b0 + 2) * HID + j] = acc2 + bb;
    g_h0[(b0 + 3) * HID + j] = acc3 + bb;
}

// ---------------- x_proj = h0 @ w_ih^T + (b_ih + b_hh) ----------------
__global__ void xproj_kernel(const float* __restrict__ b_ih, const float* __restrict__ b_hh) {
    __shared__ float sh_h[32][33];
    __shared__ float sh_w[32][64];
    int tid = threadIdx.x;
    int b0 = blockIdx.x * 32;
    int n0 = blockIdx.y * 64;
    int r  = tid & 31;
    int cg = tid >> 5;
    float acc[8];
#pragma unroll
    for (int i = 0; i < 8; i++) acc[i] = 0.f;

    for (int kc = 0; kc < HID; kc += 32) {
#pragma unroll
        for (int p = 0; p < 4; p++) {
            int e = tid + 256 * p;
            int row = e >> 5, col = e & 31;
            sh_h[row][col] = g_h0[(b0 + row) * HID + kc + col];
        }
#pragma unroll
        for (int p = 0; p < 8; p++) {
            int e = tid + 256 * p;
            int krow = e >> 6, c = e & 63;
            sh_w[krow][c] = g_wT_ih[(kc + krow) * GATES + n0 + c];
        }
        __syncthreads();
#pragma unroll
        for (int kk = 0; kk < 32; kk++) {
            float a = sh_h[r][kk];
            float4 w0 = *reinterpret_cast<const float4*>(&sh_w[kk][cg * 8]);
            float4 w1 = *reinterpret_cast<const float4*>(&sh_w[kk][cg * 8 + 4]);
            acc[0] = fmaf(a, w0.x, acc[0]);
            acc[1] = fmaf(a, w0.y, acc[1]);
            acc[2] = fmaf(a, w0.z, acc[2]);
            acc[3] = fmaf(a, w0.w, acc[3]);
            acc[4] = fmaf(a, w1.x, acc[4]);
            acc[5] = fmaf(a, w1.y, acc[5]);
            acc[6] = fmaf(a, w1.z, acc[6]);
            acc[7] = fmaf(a, w1.w, acc[7]);
        }
        __syncthreads();
    }
#pragma unroll
    for (int i = 0; i < 8; i++) {
        int n = n0 + cg * 8 + i;
        g_xproj[(b0 + r) * GATES + n] = acc[i] + b_ih[n] + b_hh[n];
    }
}

// ---------------- warp-MMA LSTM recurrence, k-split x2, DSMEM push ----------------
// 16 clusters x 8 CTAs x 512 threads (16 warps). Warps 0-7: k in [0,128);
// warps 8-15: k in [128,256). Partials combined through 2 gx buffers at the
// activation stage. Producer-push h exchange via st.shared::cluster + per-
// thread release-arrives (1024-count mbarriers); no cluster fence, no
// cluster barrier, no global h round-trip.
__global__ void __launch_bounds__(NTH, 1) __cluster_dims__(CLUSTER, 1, 1)
lstm_mma_kernel(int t0, int t1) {
    extern __shared__ char smem[];
    const uint32_t sbase = smem_u32(smem);
    float* xp  = (float*)(smem + OFF_XP);     // [16][132]
    float* gx0 = (float*)(smem + OFF_GX);     // [128][18] (k-half 0)
    float* gx1 = gx0 + 128 * 18;              // [128][18] (k-half 1)

    const int tid  = threadIdx.x;
    const int wid  = tid >> 5;
    const int lane = tid & 31;
    const int rank = blockIdx.x & (CLUSTER - 1);
    const int cl   = blockIdx.x / CLUSTER;
    const int b0   = cl * ROWS;
    const int j0   = rank * JLOC;

    const int wm  = wid & 7;          // gate-row block
    const int kq  = wid >> 3;         // k half
    const int gid = lane >> 2;
    const int kl  = (lane & 3) * 2;

    // mbarriers: 3 buffers, 1024 arrivals each (8 CTAs x 128 pusher threads)
    if (tid < 3)
        asm volatile("mbarrier.init.shared.b64 [%0], %1;"
                     :: "r"(sbase + OFF_MBAR + tid * 8), "r"(1024u) : "memory");

    // ---- W fragments into registers (once per chunk) ----
    uint32_t wHi[8][4], wLo[8][4];
    {
        const __nv_bfloat16* Wh = g_whi + rank * 32768;
        const __nv_bfloat16* Wl = g_wlo + rank * 32768;
        const int m0 = wm * 16;
#pragma unroll
        for (int kt = 0; kt < 8; kt++) {
            int k0 = kq * 128 + kt * 16 + kl;
            wHi[kt][0] = *(const uint32_t*)&Wh[(m0 + gid) * 256 + k0];
            wHi[kt][1] = *(const uint32_t*)&Wh[(m0 + gid + 8) * 256 + k0];
            wHi[kt][2] = *(const uint32_t*)&Wh[(m0 + gid) * 256 + k0 + 8];
            wHi[kt][3] = *(const uint32_t*)&Wh[(m0 + gid + 8) * 256 + k0 + 8];
            wLo[kt][0] = *(const uint32_t*)&Wl[(m0 + gid) * 256 + k0];
            wLo[kt][1] = *(const uint32_t*)&Wl[(m0 + gid + 8) * 256 + k0];
            wLo[kt][2] = *(const uint32_t*)&Wl[(m0 + gid) * 256 + k0 + 8];
            wLo[kt][3] = *(const uint32_t*)&Wl[(m0 + gid + 8) * 256 + k0 + 8];
        }
    }
    // ---- x_proj slice ----
    for (int idx = tid; idx < ROWS * 128; idx += NTH) {
        int r = idx >> 7, nl = idx & 127;
        int g = nl >> 5, jj = nl & 31;
        xp[r * 132 + nl] = g_xproj[(b0 + r) * GATES + g * HID + j0 + jj];
    }
    __syncthreads();
    // all mbarriers initialized cluster-wide before any remote arrivals
    asm volatile("barrier.cluster.arrive.aligned;" ::: "memory");
    asm volatile("barrier.cluster.wait.aligned;" ::: "memory");

    // ---- initial staging of h(t0-1) into buffer t0%3 ----
    {
        const float* hin = t0 ? (g_hs + (size_t)(t0 - 1) * BATCH * HID) : g_h0;
        char* sb = smem + OFF_SB + (t0 % 3) * BUFSZ;
        for (int i = tid; i < ROWS * (HID / 4); i += NTH) {   // 2 iters
            int row = i >> 6, c4 = i & 63;
            float4 v = ((const float4*)(hin + (size_t)(b0 + row) * HID))[c4];
            __nv_bfloat16 h0b = __float2bfloat16(v.x);
            __nv_bfloat16 h1b = __float2bfloat16(v.y);
            __nv_bfloat16 h2b = __float2bfloat16(v.z);
            __nv_bfloat16 h3b = __float2bfloat16(v.w);
            __nv_bfloat16 l0b = __float2bfloat16(v.x - __bfloat162float(h0b));
            __nv_bfloat16 l1b = __float2bfloat16(v.y - __bfloat162float(h1b));
            __nv_bfloat16 l2b = __float2bfloat16(v.z - __bfloat162float(h2b));
            __nv_bfloat16 l3b = __float2bfloat16(v.w - __bfloat162float(h3b));
            uint2 hv, lv;
            ((__nv_bfloat162*)&hv)[0] = __halves2bfloat162(h0b, h1b);
            ((__nv_bfloat162*)&hv)[1] = __halves2bfloat162(h2b, h3b);
            ((__nv_bfloat162*)&lv)[0] = __halves2bfloat162(l0b, l1b);
            ((__nv_bfloat162*)&lv)[1] = __halves2bfloat162(l2b, l3b);
            *(uint2*)(sb + row * ROWSTR + c4 * 8) = hv;
            *(uint2*)(sb + BUF_LO + row * ROWSTR + c4 * 8) = lv;
        }
    }
    __syncthreads();

    // activation cell: thread -> (ab, aj)
    const int ab = tid >> 5;
    const int aj = tid & 31;
    float cc;
    if (t0 == 0) cc = 0.f;
    else         cc = g_c[(b0 + ab) * HID + j0 + aj];

    int ph0 = 0, ph1 = 0, ph2 = 0;
    const int n0 = gid, n1 = gid + 8;

    for (int t = t0; t < t1; t++) {
        const int buf = t % 3;
        if (t > t0) {
            int par;
            if (buf == 0)      { par = ph0; ph0 ^= 1; }
            else if (buf == 1) { par = ph1; ph1 ^= 1; }
            else               { par = ph2; ph2 ^= 1; }
            mbar_wait_cluster(sbase + OFF_MBAR + buf * 8, (uint32_t)par);
        }

        // ---- MMA: 8 kt (this k half) x 2 n-tiles x 3 products ----
        float hh0[4] = {0, 0, 0, 0}, hl0[4] = {0, 0, 0, 0}, lh0[4] = {0, 0, 0, 0};
        float hh1[4] = {0, 0, 0, 0}, hl1[4] = {0, 0, 0, 0}, lh1[4] = {0, 0, 0, 0};
        {
            const char* sbhi = smem + OFF_SB + buf * BUFSZ;
            const char* sblo = sbhi + BUF_LO;
#pragma unroll
            for (int kt = 0; kt < 8; kt++) {
                int kc = kq * 128 + kt * 16 + kl;
                uint32_t b0hi = *(const uint32_t*)(sbhi + n0 * ROWSTR + 2 * kc);
                uint32_t b1hi = *(const uint32_t*)(sbhi + n0 * ROWSTR + 2 * (kc + 8));
                uint32_t b0lo = *(const uint32_t*)(sblo + n0 * ROWSTR + 2 * kc);
                uint32_t b1lo = *(const uint32_t*)(sblo + n0 * ROWSTR + 2 * (kc + 8));
                mma_bf16(hh0, wHi[kt], b0hi, b1hi);
                mma_bf16(hl0, wHi[kt], b0lo, b1lo);
                mma_bf16(lh0, wLo[kt], b0hi, b1hi);
                uint32_t c0hi = *(const uint32_t*)(sbhi + n1 * ROWSTR + 2 * kc);
                uint32_t c1hi = *(const uint32_t*)(sbhi + n1 * ROWSTR + 2 * (kc + 8));
                uint32_t c0lo = *(const uint32_t*)(sblo + n1 * ROWSTR + 2 * kc);
                uint32_t c1lo = *(const uint32_t*)(sblo + n1 * ROWSTR + 2 * (kc + 8));
                mma_bf16(hh1, wHi[kt], c0hi, c1hi);
                mma_bf16(hl1, wHi[kt], c0lo, c1lo);
                mma_bf16(lh1, wLo[kt], c0hi, c1hi);
            }
        }

        // ---- partial gate exchange: gx[kq][nl][b] ----
        {
            float* gxh = kq ? gx1 : gx0;
            const int nl0 = wm * 16 + gid;
            const int bc  = 2 * (lane & 3);
            *(float2*)&gxh[nl0 * 18 + bc] =
                make_float2(hh0[0] + hl0[0] + lh0[0], hh0[1] + hl0[1] + lh0[1]);
            *(float2*)&gxh[(nl0 + 8) * 18 + bc] =
                make_float2(hh0[2] + hl0[2] + lh0[2], hh0[3] + hl0[3] + lh0[3]);
            *(float2*)&gxh[nl0 * 18 + bc + 8] =
                make_float2(hh1[0] + hl1[0] + lh1[0], hh1[1] + hl1[1] + lh1[1]);
            *(float2*)&gxh[(nl0 + 8) * 18 + bc + 8] =
                make_float2(hh1[2] + hl1[2] + lh1[2], hh1[3] + hl1[3] + lh1[3]);
        }
        __syncthreads();

        // ---- fused activation (1 cell/thread): combine k-halves + x_proj ----
        {
            float gi = gx0[aj * 18 + ab]        + gx1[aj * 18 + ab]
                     + xp[ab * 132 + aj];
            float gf = gx0[(32 + aj) * 18 + ab] + gx1[(32 + aj) * 18 + ab]
                     + xp[ab * 132 + 32 + aj];
            float gg = gx0[(64 + aj) * 18 + ab] + gx1[(64 + aj) * 18 + ab]
                     + xp[ab * 132 + 64 + aj];
            float go = gx0[(96 + aj) * 18 + ab] + gx1[(96 + aj) * 18 + ab]
                     + xp[ab * 132 + 96 + aj];

            cc = sigmoid_x(gf) * cc + sigmoid_x(gi) * tanh_x(gg);
            float hh = sigmoid_x(go) * tanh_x(cc);

            g_hs[(size_t)t * BATCH * HID + (size_t)(b0 + ab) * HID + j0 + aj] = hh;

            __nv_bfloat16 hi = __float2bfloat16(hh);
            __nv_bfloat16 lo = __float2bfloat16(hh - __bfloat162float(hi));
            *(__nv_bfloat16*)(smem + OFF_STAGE + ab * 64 + aj * 2) = hi;
            *(__nv_bfloat16*)(smem + OFF_STAGE + 1024 + ab * 64 + aj * 2) = lo;
        }

        // ---- push slice to all 8 cluster CTAs' next buffer ----
        if (t < t1 - 1) {
            __syncthreads();                       // staging complete
            const int nbuf = (t + 1) % 3;
            if (tid < 128) {
                int islo = tid >> 6, u2 = tid & 63;
                int row = u2 >> 2, ch = u2 & 3;    // 16B chunk in 64B slice-row
                uint4 val = *(const uint4*)(smem + OFF_STAGE + islo * 1024
                                            + row * 64 + ch * 16);
                uint32_t laddr = sbase + OFF_SB + nbuf * BUFSZ + islo * BUF_LO
                               + row * ROWSTR + 2 * j0 + ch * 16;
#pragma unroll
                for (int r = 0; r < 8; r++) {
                    uint32_t ra = mapa_u32(laddr, (uint32_t)r);
                    asm volatile("st.shared::cluster.v4.b32 [%0], {%1,%2,%3,%4};"
                                 :: "r"(ra), "r"(val.x), "r"(val.y),
                                    "r"(val.z), "r"(val.w) : "memory");
                }
                // per-thread release-arrives: order this thread's stores,
                // no cluster fence, no extra CTA barrier
                uint32_t mb = sbase + OFF_MBAR + nbuf * 8;
#pragma unroll
                for (int r = 0; r < 8; r++) {
                    uint32_t ra = mapa_u32(mb, (uint32_t)r);
                    asm volatile(
                        "mbarrier.arrive.release.cluster.shared::cluster.b64 _, [%0];"
                        :: "r"(ra) : "memory");
                }
            }
        }
    }

    // spill c-state
    g_c[(b0 + ab) * HID + j0 + aj] = cc;
}

// ---------------- output projection (f32x2) ----------------
__global__ void out_kernel(const float* __restrict__ out_b, float* __restrict__ out) {
    __shared__ float2 sh_a2[64][17];
    __shared__ float  sh_w[16][128];
    int tid = threadIdx.x;
    int r0 = blockIdx.x * 64;
    int rr = tid & 15;
    int cg = tid >> 4;

    unsigned long long acc[4][4];
#pragma unroll
    for (int q = 0; q < 4; q++)
#pragma unroll
        for (int i = 0; i < 4; i++) acc[q][i] = 0ull;

    for (int kc = 0; kc < HID; kc += 16) {
#pragma unroll
        for (int p = 0; p < 4; p++) {
            int e = tid + 256 * p;
            int row = e >> 4, kk = e & 15;
            float v = g_hs[(size_t)(r0 + row) * HID + kc + kk];
            sh_a2[row][kk] = make_float2(v, v);
        }
#pragma unroll
        for (int p = 0; p < 8; p++) {
            int e = tid + 256 * p;
            int krow = e >> 7, c = e & 127;
            int c8 = c >> 3, i = c & 7;
            sh_w[krow][(i >> 2) * 64 + c8 * 4 + (i & 3)] = g_outT[(kc + krow) * OUTD + c];
        }
        __syncthreads();
#pragma unroll
        for (int kk = 0; kk < 16; kk++) {
            unsigned long long p0 = *(const unsigned long long*)&sh_a2[rr][kk];
            unsigned long long p1 = *(const unsigned long long*)&sh_a2[rr + 16][kk];
            unsigned long long p2 = *(const unsigned long long*)&sh_a2[rr + 32][kk];
            unsigned long long p3 = *(const unsigned long long*)&sh_a2[rr + 48][kk];
            ulonglong2 wA = *(const ulonglong2*)(&sh_w[kk][cg * 4]);
            ulonglong2 wB = *(const ulonglong2*)(&sh_w[kk][64 + cg * 4]);
            fma2(acc[0][0], p0, wA.x); fma2(acc[0][1], p0, wA.y);
            fma2(acc[0][2], p0, wB.x); fma2(acc[0][3], p0, wB.y);
            fma2(acc[1][0], p1, wA.x); fma2(acc[1][1], p1, wA.y);
            fma2(acc[1][2], p1, wB.x); fma2(acc[1][3], p1, wB.y);
            fma2(acc[2][0], p2, wA.x); fma2(acc[2][1], p2, wA.y);
            fma2(acc[2][2], p2, wB.x); fma2(acc[2][3], p2, wB.y);
            fma2(acc[3][0], p3, wA.x); fma2(acc[3][1], p3, wA.y);
            fma2(acc[3][2], p3, wB.x); fma2(acc[3][3], p3, wB.y);
        }
        __syncthreads();
    }

    float ob[8];
#pragma unroll
    for (int i = 0; i < 8; i++) ob[i] = out_b[cg * 8 + i];

#pragma unroll
    for (int q = 0; q < 4; q++) {
        int rIdx = r0 + rr + 16 * q;
        int t = rIdx >> 8;
        int b = rIdx & 255;
        float* dst = out + ((size_t)b * SEQ + t) * OUTD + cg * 8;
#pragma unroll
        for (int i = 0; i < 4; i++) {
            float2 f = upk2(acc[q][i]);
            dst[2 * i]     = f.x + ob[2 * i];
            dst[2 * i + 1] = f.y + ob[2 * i + 1];
        }
    }
}

// ---------------- launch ----------------
extern "C" void kernel_launch(void* const* d_in, const int* in_sizes, int n_in,
                              void* d_out, int out_size) {
    const float* z     = (const float*)d_in[0];
    const float* fc_w  = (const float*)d_in[1];
    const float* fc_b  = (const float*)d_in[2];
    const float* w_ih  = (const float*)d_in[3];
    const float* w_hh  = (const float*)d_in[4];
    const float* b_ih  = (const float*)d_in[5];
    const float* b_hh  = (const float*)d_in[6];
    const float* out_w = (const float*)d_in[7];
    const float* out_b = (const float*)d_in[8];
    float* out = (float*)d_out;

    cudaFuncSetAttribute(lstm_mma_kernel,
                         cudaFuncAttributeMaxDynamicSharedMemorySize, SMEM_LSTM);

    // launch 0: weight prep
    prep_kernel<<<560, 256>>>(w_hh, w_ih, fc_w, out_w);
    // launch 1: h0
    h0_kernel<<<BATCH / 4, 256>>>(z, fc_b);
    // launch 2: x_proj
    xproj_kernel<<<dim3(BATCH / 32, GATES / 64), 256>>>(b_ih, b_hh);
    // launches 3..6: recurrence, 4 chunks of 128 steps
    for (int c = 0; c < SEQ / CHUNK; c++) {
        lstm_mma_kernel<<<NCLUSTER * CLUSTER, NTH, SMEM_LSTM>>>(
            c * CHUNK, (c + 1) * CHUNK);
    }
    // launch 7: output projection
    out_kernel<<<(SEQ * BATCH) / 64, 256>>>(out_b, out);
}

// round 15
// speedup vs baseline: 1.1443x; 1.1443x over previous
#include <cuda_runtime.h>
#include <cuda_bf16.h>
#include <math.h>
#include <stdint.h>

#define BATCH   256
#define LATENT  64
#define HID     256
#define GATES   1024
#define OUTD    128
#define SEQ     512
#define CHUNK   128

#define CLUSTER   8
#define NCLUSTER  16
#define ROWS      16        // batch rows per cluster (2 groups of 8)
#define GROWS     8         // rows per group
#define JLOC      32
#define NTH       256

// ---- dynamic smem layout (bytes) ----
#define ROWSTR   528                      // 264 bf16 per tile row
#define TILE_LO  4224                     // 8 rows * 528 (hi half)
#define TILESZ   8448                     // hi + lo
#define OFF_SB    0                       // 2 group tiles
#define OFF_XP    (2 * TILESZ)            // 16896 : float[16][132]
#define OFF_GX    (OFF_XP + 16*132*4)     // 25344 : float[128][9]
#define OFF_MBAR  (OFF_GX + 128*9*4)      // 29952 : 4 mbarriers
#define SMEM_LSTM (OFF_MBAR + 64)         // 30016

// ---------------- persistent device scratch ----------------
__device__ float g_wT_ih[HID * GATES];
__device__ float g_fcwT [LATENT * HID];
__device__ float g_outT [HID * OUTD];
__device__ float g_h0   [BATCH * HID];
__device__ float g_c    [BATCH * HID];
__device__ float g_xproj[BATCH * GATES];
__device__ float g_hs   [SEQ * BATCH * HID];
__device__ __nv_bfloat16 g_whi[CLUSTER * 128 * 256];   // per-rank [nl][k]
__device__ __nv_bfloat16 g_wlo[CLUSTER * 128 * 256];

// ---------------- helpers ----------------
__device__ __forceinline__ void fma2(unsigned long long& d, unsigned long long a,
                                     unsigned long long b) {
    asm("fma.rn.f32x2 %0, %1, %2, %0;" : "+l"(d) : "l"(a), "l"(b));
}
__device__ __forceinline__ float2 upk2(unsigned long long v) {
    float2 r;
    asm("mov.b64 {%0, %1}, %2;" : "=f"(r.x), "=f"(r.y) : "l"(v));
    return r;
}
__device__ __forceinline__ float sigmoid_x(float x) {
    return __frcp_rn(1.f + __expf(-x));
}
__device__ __forceinline__ float tanh_x(float x) {
    return 1.f - 2.f * __frcp_rn(1.f + __expf(2.f * x));
}
__device__ __forceinline__ uint32_t smem_u32(const void* p) {
    uint32_t a;
    asm("{ .reg .u64 t; cvta.to.shared.u64 t, %1; cvt.u32.u64 %0, t; }" : "=r"(a) : "l"(p));
    return a;
}
__device__ __forceinline__ uint32_t mapa_u32(uint32_t addr, uint32_t rank) {
    uint32_t r;
    asm("mapa.shared::cluster.u32 %0, %1, %2;" : "=r"(r) : "r"(addr), "r"(rank));
    return r;
}
__device__ __forceinline__ void mma_bf16(float d[4], const uint32_t a[4],
                                         uint32_t b0, uint32_t b1) {
    asm volatile(
        "mma.sync.aligned.m16n8k16.row.col.f32.bf16.bf16.f32 "
        "{%0,%1,%2,%3}, {%4,%5,%6,%7}, {%8,%9}, {%0,%1,%2,%3};"
        : "+f"(d[0]), "+f"(d[1]), "+f"(d[2]), "+f"(d[3])
        : "r"(a[0]), "r"(a[1]), "r"(a[2]), "r"(a[3]), "r"(b0), "r"(b1));
}
__device__ __forceinline__ void mbar_wait_cluster(uint32_t mbar, uint32_t parity) {
    asm volatile("{\n\t.reg .pred P1;\n\t"
                 "WAIT_LOOP_%=:\n\t"
                 "mbarrier.try_wait.parity.acquire.cluster.shared::cta.b64 P1, [%0], %1, 0x989680;\n\t"
                 "@P1 bra.uni WAIT_DONE_%=;\n\t"
                 "bra.uni WAIT_LOOP_%=;\n\t"
                 "WAIT_DONE_%=:\n\t}" :: "r"(mbar), "r"(parity) : "memory");
}
// publish group signal: global h stores already done + __syncthreads'ed.
// threads 0..7: cumulative gpu fence, then ONE release-arrive at each peer.
__device__ __forceinline__ void publish_signal(uint32_t sbase, int g, int idx, int tid) {
    if (tid < 8) {
        asm volatile("fence.acq_rel.gpu;" ::: "memory");
        uint32_t mb = sbase + OFF_MBAR + (g * 2 + idx) * 8;
        uint32_t ra = mapa_u32(mb, (uint32_t)tid);
        asm volatile("mbarrier.arrive.release.cluster.shared::cluster.b64 _, [%0];"
                     :: "r"(ra) : "memory");
    }
}
// convert 8 fp32 -> hi/lo bf16, store 16B each into a group tile
__device__ __forceinline__ void sts_conv(char* tile, int row, int cb,
                                         float4 va, float4 vb) {
    float v[8] = {va.x, va.y, va.z, va.w, vb.x, vb.y, vb.z, vb.w};
    __nv_bfloat16 hi[8], lo[8];
#pragma unroll
    for (int i = 0; i < 8; i++) {
        hi[i] = __float2bfloat16(v[i]);
        lo[i] = __float2bfloat16(v[i] - __bfloat162float(hi[i]));
    }
    *(uint4*)(tile + row * ROWSTR + cb * 16) = *(uint4*)hi;
    *(uint4*)(tile + TILE_LO + row * ROWSTR + cb * 16) = *(uint4*)lo;
}
// one group phase MMA: D[16 gate-rows(warp), 8 batch] over k=256, 3 split products
__device__ __forceinline__ void phase_mma(const char* tb,
                                          const uint32_t wHi[16][4],
                                          const uint32_t wLo[16][4],
                                          int gid, int kl, float dout[4]) {
    float hh[4] = {0, 0, 0, 0}, hl[4] = {0, 0, 0, 0}, lh[4] = {0, 0, 0, 0};
    const char* tl = tb + TILE_LO;
#pragma unroll
    for (int kt = 0; kt < 16; kt++) {
        int kc = kt * 16 + kl;
        uint32_t bhi0 = *(const uint32_t*)(tb + gid * ROWSTR + 2 * kc);
        uint32_t bhi1 = *(const uint32_t*)(tb + gid * ROWSTR + 2 * (kc + 8));
        uint32_t blo0 = *(const uint32_t*)(tl + gid * ROWSTR + 2 * kc);
        uint32_t blo1 = *(const uint32_t*)(tl + gid * ROWSTR + 2 * (kc + 8));
        mma_bf16(hh, wHi[kt], bhi0, bhi1);
        mma_bf16(hl, wHi[kt], blo0, blo1);
        mma_bf16(lh, wLo[kt], bhi0, bhi1);
    }
#pragma unroll
    for (int i = 0; i < 4; i++) dout[i] = hh[i] + hl[i] + lh[i];
}

// ---------------- prep: W split (bf16 hi/lo) + transposes ----------------
__device__ __forceinline__ void do_transpose(const float* __restrict__ src,
                                             float* __restrict__ dst,
                                             int R, int C, int bx, int by, int tid) {
    __shared__ float tile[32][33];
    int tx = tid & 31;
    int ty = tid >> 5;
#pragma unroll
    for (int p = 0; p < 32; p += 8) {
        int r = by * 32 + ty + p, c = bx * 32 + tx;
        if (r < R && c < C) tile[ty + p][tx] = src[r * C + c];
    }
    __syncthreads();
#pragma unroll
    for (int p = 0; p < 32; p += 8) {
        int r = by * 32 + tx, c = bx * 32 + ty + p;
        if (r < R && c < C) dst[c * R + r] = tile[tx][ty + p];
    }
}

__global__ void prep_kernel(const float* __restrict__ w_hh, const float* __restrict__ w_ih,
                            const float* __restrict__ fc_w, const float* __restrict__ out_w) {
    int b = blockIdx.x;
    int tid = threadIdx.x;
    if (b < 256) {
        int rank = b >> 5, rg = b & 31;
        int k = tid;
#pragma unroll
        for (int q = 0; q < 4; q++) {
            int nl = rg * 4 + q;
            int g = nl >> 5, jj = nl & 31;
            float w = w_hh[(g * 256 + rank * JLOC + jj) * HID + k];
            __nv_bfloat16 hi = __float2bfloat16(w);
            __nv_bfloat16 lo = __float2bfloat16(w - __bfloat162float(hi));
            uint32_t idx = rank * 32768 + nl * 256 + k;
            g_whi[idx] = hi;
            g_wlo[idx] = lo;
        }
    } else if (b < 512) {
        int t = b - 256;
        do_transpose(w_ih, g_wT_ih, GATES, HID, t & 7, t >> 3, tid);
    } else if (b < 528) {
        int t = b - 512;
        do_transpose(fc_w, g_fcwT, HID, LATENT, t & 1, t >> 1, tid);
    } else {
        int t = b - 528;
        do_transpose(out_w, g_outT, OUTD, HID, t & 7, t >> 3, tid);
    }
}

// ---------------- h0 = z @ fc_w^T + fc_b ----------------
__global__ void h0_kernel(const float* __restrict__ z, const float* __restrict__ fc_b) {
    __shared__ float sh_z[4][LATENT];
    int tid = threadIdx.x;
    int b0 = blockIdx.x * 4;
    {
        int row = tid >> 6, k = tid & 63;
        sh_z[row][k] = z[(b0 + row) * LATENT + k];
    }
    __syncthreads();
    float acc0 = 0.f, acc1 = 0.f, acc2 = 0.f, acc3 = 0.f;
    int j = tid;
#pragma unroll 8
    for (int k = 0; k < LATENT; k++) {
        float w = g_fcwT[k * HID + j];
        acc0 = fmaf(sh_z[0][k], w, acc0);
        acc1 = fmaf(sh_z[1][k], w, acc1);
        acc2 = fmaf(sh_z[2][k], w, acc2);
        acc3 = fmaf(sh_z[3][k], w, acc3);
    }
    float bb = fc_b[j];
    g_h0[(b0 + 0) * HID + j] = acc0 + bb;
    g_h0[(b0 + 1) * HID + j] = acc1 + bb;
    g_h0[(b0 + 2) * HID + j] = acc2 + bb;
    g_h0[(b0 + 3) * HID + j] = acc3 + bb;
}

// ---------------- x_proj = h0 @ w_ih^T + (b_ih + b_hh) ----------------
__global__ void xproj_kernel(const float* __restrict__ b_ih, const float* __restrict__ b_hh) {
    __shared__ float sh_h[32][33];
    __shared__ float sh_w[32][64];
    int tid = threadIdx.x;
    int b0 = blockIdx.x * 32;
    int n0 = blockIdx.y * 64;
    int r  = tid & 31;
    int cg = tid >> 5;
    float acc[8];
#pragma unroll
    for (int i = 0; i < 8; i++) acc[i] = 0.f;

    for (int kc = 0; kc < HID; kc += 32) {
#pragma unroll
        for (int p = 0; p < 4; p++) {
            int e = tid + 256 * p;
            int row = e >> 5, col = e & 31;
            sh_h[row][col] = g_h0[(b0 + row) * HID + kc + col];
        }
#pragma unroll
        for (int p = 0; p < 8; p++) {
            int e = tid + 256 * p;
            int krow = e >> 6, c = e & 63;
            sh_w[krow][c] = g_wT_ih[(kc + krow) * GATES + n0 + c];
        }
        __syncthreads();
#pragma unroll
        for (int kk = 0; kk < 32; kk++) {
            float a = sh_h[r][kk];
            float4 w0 = *reinterpret_cast<const float4*>(&sh_w[kk][cg * 8]);
            float4 w1 = *reinterpret_cast<const float4*>(&sh_w[kk][cg * 8 + 4]);
            acc[0] = fmaf(a, w0.x, acc[0]);
            acc[1] = fmaf(a, w0.y, acc[1]);
            acc[2] = fmaf(a, w0.z, acc[2]);
            acc[3] = fmaf(a, w0.w, acc[3]);
            acc[4] = fmaf(a, w1.x, acc[4]);
            acc[5] = fmaf(a, w1.y, acc[5]);
            acc[6] = fmaf(a, w1.z, acc[6]);
            acc[7] = fmaf(a, w1.w, acc[7]);
        }
        __syncthreads();
    }
#pragma unroll
    for (int i = 0; i < 8; i++) {
        int n = n0 + cg * 8 + i;
        g_xproj[(b0 + r) * GATES + n] = acc[i] + b_ih[n] + b_hh[n];
    }
}

// ---------------- dual-pipeline warp-MMA LSTM recurrence ----------------
// 16 clusters x 8 CTAs x 256 threads. The 16 batch rows split into two
// INDEPENDENT groups of 8; each step runs two phases. While phase g
// computes (MMA n=8 + activations), the other group's published h is being
// fetched (LDG.cg held in regs) -- wait/LDG/fence latencies hide under
// compute. Exchange via global fp32 h + per-group mbarrier signals
// (8 arrivals each, fence.acq_rel.gpu + single release-arrive per CTA).
__global__ void __launch_bounds__(NTH, 1) __cluster_dims__(CLUSTER, 1, 1)
lstm_mma_kernel(int t0, int t1) {
    extern __shared__ char smem[];
    const uint32_t sbase = smem_u32(smem);
    char*  tile0 = smem + OFF_SB;             // group 0 tile (hi+lo)
    char*  tile1 = tile0 + TILESZ;            // group 1 tile
    float* xp    = (float*)(smem + OFF_XP);   // [16][132]
    float* gx    = (float*)(smem + OFF_GX);   // [128][9]

    const int tid  = threadIdx.x;
    const int wid  = tid >> 5;
    const int lane = tid & 31;
    const int rank = blockIdx.x & (CLUSTER - 1);
    const int cl   = blockIdx.x / CLUSTER;
    const int b0   = cl * ROWS;
    const int j0   = rank * JLOC;

    const int gid = lane >> 2;
    const int kl  = (lane & 3) * 2;

    // 4 mbarriers: (group, idx) with 8 arrivals each
    if (tid < 4)
        asm volatile("mbarrier.init.shared.b64 [%0], %1;"
                     :: "r"(sbase + OFF_MBAR + tid * 8), "r"(8u) : "memory");

    // ---- W fragments into registers ----
    uint32_t wHi[16][4], wLo[16][4];
    {
        const __nv_bfloat16* Wh = g_whi + rank * 32768;
        const __nv_bfloat16* Wl = g_wlo + rank * 32768;
        const int m0 = wid * 16;
#pragma unroll
        for (int kt = 0; kt < 16; kt++) {
            int k0 = kt * 16 + kl;
            wHi[kt][0] = *(const uint32_t*)&Wh[(m0 + gid) * 256 + k0];
            wHi[kt][1] = *(const uint32_t*)&Wh[(m0 + gid + 8) * 256 + k0];
            wHi[kt][2] = *(const uint32_t*)&Wh[(m0 + gid) * 256 + k0 + 8];
            wHi[kt][3] = *(const uint32_t*)&Wh[(m0 + gid + 8) * 256 + k0 + 8];
            wLo[kt][0] = *(const uint32_t*)&Wl[(m0 + gid) * 256 + k0];
            wLo[kt][1] = *(const uint32_t*)&Wl[(m0 + gid + 8) * 256 + k0];
            wLo[kt][2] = *(const uint32_t*)&Wl[(m0 + gid) * 256 + k0 + 8];
            wLo[kt][3] = *(const uint32_t*)&Wl[(m0 + gid + 8) * 256 + k0 + 8];
        }
    }
    // ---- x_proj slice ----
    for (int idx = tid; idx < ROWS * 128; idx += NTH) {
        int r = idx >> 7, nl = idx & 127;
        int g = nl >> 5, jj = nl & 31;
        xp[r * 132 + nl] = g_xproj[(b0 + r) * GATES + g * HID + j0 + jj];
    }
    __syncthreads();
    asm volatile("barrier.cluster.arrive.aligned;" ::: "memory");
    asm volatile("barrier.cluster.wait.aligned;" ::: "memory");

    // ---- prologue: stage both tiles from h(t0-1) ----
    const int srow = tid >> 5;       // 0..7
    const int scb  = tid & 31;       // 32 col-blocks of 8
    {
        const float* hin = t0 ? (g_hs + (size_t)(t0 - 1) * BATCH * HID) : g_h0;
        {
            const float4* p = (const float4*)(hin + (size_t)(b0 + srow) * HID) + scb * 2;
            sts_conv(tile0, srow, scb, __ldcg(p), __ldcg(p + 1));
        }
        {
            const float4* p = (const float4*)(hin + (size_t)(b0 + 8 + srow) * HID) + scb * 2;
            sts_conv(tile1, srow, scb, __ldcg(p), __ldcg(p + 1));
        }
    }
    __syncthreads();

    // activation cell: (group-phase row ab, col aj)
    const int ab = tid >> 5;
    const int aj = tid & 31;
    float c0, c1;
    if (t0 == 0) { c0 = 0.f; c1 = 0.f; }
    else {
        c0 = g_c[(b0 + ab) * HID + j0 + aj];
        c1 = g_c[(b0 + 8 + ab) * HID + j0 + aj];
    }

    const int nl0 = wid * 16 + gid;
    const int bc  = 2 * (lane & 3);
    int q00 = 0, q01 = 0, q10 = 0, q11 = 0;   // wait parities: q[g][idx]

    for (int t = t0; t < t1; t++) {
        // ================= PHASE 0 (group 0, step t) =================
        float4 ha, hb;
        if (t > t0) {
            // wait sig_g1[t] (h_g1(t-1) published during phase1 of t-1)
            int idx = t & 1;
            int par = idx ? q11 : q10;
            if (idx) q11 ^= 1; else q10 ^= 1;
            mbar_wait_cluster(sbase + OFF_MBAR + (2 + idx) * 8, (uint32_t)par);
            const float4* p = (const float4*)(g_hs + (size_t)(t - 1) * BATCH * HID
                                              + (size_t)(b0 + 8 + srow) * HID) + scb * 2;
            ha = __ldcg(p); hb = __ldcg(p + 1);
        }
        {
            float d[4];
            phase_mma(tile0, wHi, wLo, gid, kl, d);
            gx[nl0 * 9 + bc] = d[0];
            gx[nl0 * 9 + bc + 1] = d[1];
            gx[(nl0 + 8) * 9 + bc] = d[2];
            gx[(nl0 + 8) * 9 + bc + 1] = d[3];
        }
        __syncthreads();
        {
            const float* xr = xp + ab * 132;
            float gi = gx[aj * 9 + ab]        + xr[aj];
            float gf = gx[(32 + aj) * 9 + ab] + xr[32 + aj];
            float gg = gx[(64 + aj) * 9 + ab] + xr[64 + aj];
            float go = gx[(96 + aj) * 9 + ab] + xr[96 + aj];
            c0 = sigmoid_x(gf) * c0 + sigmoid_x(gi) * tanh_x(gg);
            float hh = sigmoid_x(go) * tanh_x(c0);
            g_hs[(size_t)t * BATCH * HID + (size_t)(b0 + ab) * HID + j0 + aj] = hh;
        }
        __syncthreads();
        if (t < t1 - 1) publish_signal(sbase, 0, (t + 1) & 1, tid);
        if (t > t0) {
            sts_conv(tile1, srow, scb, ha, hb);   // h_g1(t-1) for phase 1
            __syncthreads();
        }

        // ================= PHASE 1 (group 1, step t) =================
        if (t < t1 - 1) {
            // wait sig_g0[t+1] (h_g0(t), just published incl. by ourselves)
            int idx = (t + 1) & 1;
            int par = idx ? q01 : q00;
            if (idx) q01 ^= 1; else q00 ^= 1;
            mbar_wait_cluster(sbase + OFF_MBAR + idx * 8, (uint32_t)par);
            const float4* p = (const float4*)(g_hs + (size_t)t * BATCH * HID
                                              + (size_t)(b0 + srow) * HID) + scb * 2;
            ha = __ldcg(p); hb = __ldcg(p + 1);
        }
        {
            float d[4];
            phase_mma(tile1, wHi, wLo, gid, kl, d);
            gx[nl0 * 9 + bc] = d[0];
            gx[nl0 * 9 + bc + 1] = d[1];
            gx[(nl0 + 8) * 9 + bc] = d[2];
            gx[(nl0 + 8) * 9 + bc + 1] = d[3];
        }
        __syncthreads();
        {
            const float* xr = xp + (8 + ab) * 132;
            float gi = gx[aj * 9 + ab]        + xr[aj];
            float gf = gx[(32 + aj) * 9 + ab] + xr[32 + aj];
            float gg = gx[(64 + aj) * 9 + ab] + xr[64 + aj];
            float go = gx[(96 + aj) * 9 + ab] + xr[96 + aj];
            c1 = sigmoid_x(gf) * c1 + sigmoid_x(gi) * tanh_x(gg);
            float hh = sigmoid_x(go) * tanh_x(c1);
            g_hs[(size_t)t * BATCH * HID + (size_t)(b0 + 8 + ab) * HID + j0 + aj] = hh;
        }
        __syncthreads();
        if (t < t1 - 1) {
            publish_signal(sbase, 1, (t + 1) & 1, tid);
            sts_conv(tile0, srow, scb, ha, hb);   // h_g0(t) for next phase 0
            __syncthreads();
        }
    }

    // spill c-state
    g_c[(b0 + ab) * HID + j0 + aj]     = c0;
    g_c[(b0 + 8 + ab) * HID + j0 + aj] = c1;
}

// ---------------- output projection (f32x2) ----------------
__global__ void out_kernel(const float* __restrict__ out_b, float* __restrict__ out) {
    __shared__ float2 sh_a2[64][17];
    __shared__ float  sh_w[16][128];
    int tid = threadIdx.x;
    int r0 = blockIdx.x * 64;
    int rr = tid & 15;
    int cg = tid >> 4;

    unsigned long long acc[4][4];
#pragma unroll
    for (int q = 0; q < 4; q++)
#pragma unroll
        for (int i = 0; i < 4; i++) acc[q][i] = 0ull;

    for (int kc = 0; kc < HID; kc += 16) {
#pragma unroll
        for (int p = 0; p < 4; p++) {
            int e = tid + 256 * p;
            int row = e >> 4, kk = e & 15;
            float v = g_hs[(size_t)(r0 + row) * HID + kc + kk];
            sh_a2[row][kk] = make_float2(v, v);
        }
#pragma unroll
        for (int p = 0; p < 8; p++) {
            int e = tid + 256 * p;
            int krow = e >> 7, c = e & 127;
            int c8 = c >> 3, i = c & 7;
            sh_w[krow][(i >> 2) * 64 + c8 * 4 + (i & 3)] = g_outT[(kc + krow) * OUTD + c];
        }
        __syncthreads();
#pragma unroll
        for (int kk = 0; kk < 16; kk++) {
            unsigned long long p0 = *(const unsigned long long*)&sh_a2[rr][kk];
            unsigned long long p1 = *(const unsigned long long*)&sh_a2[rr + 16][kk];
            unsigned long long p2 = *(const unsigned long long*)&sh_a2[rr + 32][kk];
            unsigned long long p3 = *(const unsigned long long*)&sh_a2[rr + 48][kk];
            ulonglong2 wA = *(const ulonglong2*)(&sh_w[kk][cg * 4]);
            ulonglong2 wB = *(const ulonglong2*)(&sh_w[kk][64 + cg * 4]);
            fma2(acc[0][0], p0, wA.x); fma2(acc[0][1], p0, wA.y);
            fma2(acc[0][2], p0, wB.x); fma2(acc[0][3], p0, wB.y);
            fma2(acc[1][0], p1, wA.x); fma2(acc[1][1], p1, wA.y);
            fma2(acc[1][2], p1, wB.x); fma2(acc[1][3], p1, wB.y);
            fma2(acc[2][0], p2, wA.x); fma2(acc[2][1], p2, wA.y);
            fma2(acc[2][2], p2, wB.x); fma2(acc[2][3], p2, wB.y);
            fma2(acc[3][0], p3, wA.x); fma2(acc[3][1], p3, wA.y);
            fma2(acc[3][2], p3, wB.x); fma2(acc[3][3], p3, wB.y);
        }
        __syncthreads();
    }

    float ob[8];
#pragma unroll
    for (int i = 0; i < 8; i++) ob[i] = out_b[cg * 8 + i];

#pragma unroll
    for (int q = 0; q < 4; q++) {
        int rIdx = r0 + rr + 16 * q;
        int t = rIdx >> 8;
        int b = rIdx & 255;
        float* dst = out + ((size_t)b * SEQ + t) * OUTD + cg * 8;
#pragma unroll
        for (int i = 0; i < 4; i++) {
            float2 f = upk2(acc[q][i]);
            dst[2 * i]     = f.x + ob[2 * i];
            dst[2 * i + 1] = f.y + ob[2 * i + 1];
        }
    }
}

// ---------------- launch ----------------
extern "C" void kernel_launch(void* const* d_in, const int* in_sizes, int n_in,
                              void* d_out, int out_size) {
    const float* z     = (const float*)d_in[0];
    const float* fc_w  = (const float*)d_in[1];
    const float* fc_b  = (const float*)d_in[2];
    const float* w_ih  = (const float*)d_in[3];
    const float* w_hh  = (const float*)d_in[4];
    const float* b_ih  = (const float*)d_in[5];
    const float* b_hh  = (const float*)d_in[6];
    const float* out_w = (const float*)d_in[7];
    const float* out_b = (const float*)d_in[8];
    float* out = (float*)d_out;

    cudaFuncSetAttribute(lstm_mma_kernel,
                         cudaFuncAttributeMaxDynamicSharedMemorySize, SMEM_LSTM);

    // launch 0: weight prep
    prep_kernel<<<560, 256>>>(w_hh, w_ih, fc_w, out_w);
    // launch 1: h0
    h0_kernel<<<BATCH / 4, 256>>>(z, fc_b);
    // launch 2: x_proj
    xproj_kernel<<<dim3(BATCH / 32, GATES / 64), 256>>>(b_ih, b_hh);
    // launches 3..6: recurrence, 4 chunks of 128 steps
    for (int c = 0; c < SEQ / CHUNK; c++) {
        lstm_mma_kernel<<<NCLUSTER * CLUSTER, NTH, SMEM_LSTM>>>(
            c * CHUNK, (c + 1) * CHUNK);
    }
    // launch 7: output projection
    out_kernel<<<(SEQ * BATCH) / 64, 256>>>(out_b, out);
}

// round 16
// speedup vs baseline: 1.4994x; 1.3103x over previous
#include <cuda_runtime.h>
#include <cuda_bf16.h>
#include <math.h>
#include <stdint.h>

#define BATCH   256
#define LATENT  64
#define HID     256
#define GATES   1024
#define OUTD    128
#define SEQ     512
#define CHUNK   128

#define CLUSTER   8
#define NCLUSTER  16
#define ROWS      16
#define JLOC      32
#define NTH       256

// ---- dynamic smem layout (bytes) ----
// B tiles: [row][k-pair] interleaved: 8B unit = [hi bf16x2][lo bf16x2].
// Row = 128 k-pairs * 8B = 1024B + 32 pad -> 1056.
#define ROWSTR   1056
#define BUFSZ    (ROWS * ROWSTR)          // 16896
#define OFF_SB    0                       // 2 buffers (step parity)
#define OFF_XP    (2 * BUFSZ)             // 33792 : float[16][132]
#define OFF_GX    (OFF_XP + 16*132*4)     // 42240 : float[128][18]
#define SMEM_LSTM (OFF_GX + 128*18*4)     // 51456

// ---------------- persistent device scratch ----------------
__device__ float g_wT_ih[HID * GATES];
__device__ float g_fcwT [LATENT * HID];
__device__ float g_outT [HID * OUTD];
__device__ float g_h0   [BATCH * HID];
__device__ float g_c    [BATCH * HID];
__device__ float g_xproj[BATCH * GATES];
__device__ float g_hs   [SEQ * BATCH * HID];
__device__ __nv_bfloat16 g_whi[CLUSTER * 128 * 256];   // per-rank [nl][k]
__device__ __nv_bfloat16 g_wlo[CLUSTER * 128 * 256];

// ---------------- helpers ----------------
__device__ __forceinline__ void fma2(unsigned long long& d, unsigned long long a,
                                     unsigned long long b) {
    asm("fma.rn.f32x2 %0, %1, %2, %0;" : "+l"(d) : "l"(a), "l"(b));
}
__device__ __forceinline__ float2 upk2(unsigned long long v) {
    float2 r;
    asm("mov.b64 {%0, %1}, %2;" : "=f"(r.x), "=f"(r.y) : "l"(v));
    return r;
}
__device__ __forceinline__ float sigmoid_x(float x) {
    return __frcp_rn(1.f + __expf(-x));
}
__device__ __forceinline__ float tanh_x(float x) {
    return 1.f - 2.f * __frcp_rn(1.f + __expf(2.f * x));
}
__device__ __forceinline__ uint32_t smem_u32(const void* p) {
    uint32_t a;
    asm("{ .reg .u64 t; cvta.to.shared.u64 t, %1; cvt.u32.u64 %0, t; }" : "=r"(a) : "l"(p));
    return a;
}
__device__ __forceinline__ uint32_t mapa_u32(uint32_t addr, uint32_t rank) {
    uint32_t r;
    asm("mapa.shared::cluster.u32 %0, %1, %2;" : "=r"(r) : "r"(addr), "r"(rank));
    return r;
}
__device__ __forceinline__ void mma_bf16(float d[4], const uint32_t a[4],
                                         uint32_t b0, uint32_t b1) {
    asm volatile(
        "mma.sync.aligned.m16n8k16.row.col.f32.bf16.bf16.f32 "
        "{%0,%1,%2,%3}, {%4,%5,%6,%7}, {%8,%9}, {%0,%1,%2,%3};"
        : "+f"(d[0]), "+f"(d[1]), "+f"(d[2]), "+f"(d[3])
        : "r"(a[0]), "r"(a[1]), "r"(a[2]), "r"(a[3]), "r"(b0), "r"(b1));
}
// pack 8 fp32 into interleaved hi/lo pairs, store 4 x 8B at pair base p0
__device__ __forceinline__ void sts_conv8(char* tile, int row, int cb,
                                          float4 va, float4 vb) {
    float v[8] = {va.x, va.y, va.z, va.w, vb.x, vb.y, vb.z, vb.w};
#pragma unroll
    for (int q = 0; q < 4; q++) {
        __nv_bfloat16 h0 = __float2bfloat16(v[2 * q]);
        __nv_bfloat16 h1 = __float2bfloat16(v[2 * q + 1]);
        __nv_bfloat16 l0 = __float2bfloat16(v[2 * q] - __bfloat162float(h0));
        __nv_bfloat16 l1 = __float2bfloat16(v[2 * q + 1] - __bfloat162float(h1));
        __nv_bfloat162 hp = __halves2bfloat162(h0, h1);
        __nv_bfloat162 lp = __halves2bfloat162(l0, l1);
        uint2 u;
        *(__nv_bfloat162*)&u.x = hp;
        *(__nv_bfloat162*)&u.y = lp;
        *(uint2*)(tile + row * ROWSTR + cb * 32 + q * 8) = u;
    }
}

// ---------------- prep: W split (bf16 hi/lo) + transposes ----------------
__device__ __forceinline__ void do_transpose(const float* __restrict__ src,
                                             float* __restrict__ dst,
                                             int R, int C, int bx, int by, int tid) {
    __shared__ float tile[32][33];
    int tx = tid & 31;
    int ty = tid >> 5;
#pragma unroll
    for (int p = 0; p < 32; p += 8) {
        int r = by * 32 + ty + p, c = bx * 32 + tx;
        if (r < R && c < C) tile[ty + p][tx] = src[r * C + c];
    }
    __syncthreads();
#pragma unroll
    for (int p = 0; p < 32; p += 8) {
        int r = by * 32 + tx, c = bx * 32 + ty + p;
        if (r < R && c < C) dst[c * R + r] = tile[tx][ty + p];
    }
}

__global__ void prep_kernel(const float* __restrict__ w_hh, const float* __restrict__ w_ih,
                            const float* __restrict__ fc_w, const float* __restrict__ out_w) {
    int b = blockIdx.x;
    int tid = threadIdx.x;
    if (b < 256) {
        int rank = b >> 5, rg = b & 31;
        int k = tid;
#pragma unroll
        for (int q = 0; q < 4; q++) {
            int nl = rg * 4 + q;
            int g = nl >> 5, jj = nl & 31;
            float w = w_hh[(g * 256 + rank * JLOC + jj) * HID + k];
            __nv_bfloat16 hi = __float2bfloat16(w);
            __nv_bfloat16 lo = __float2bfloat16(w - __bfloat162float(hi));
            uint32_t idx = rank * 32768 + nl * 256 + k;
            g_whi[idx] = hi;
            g_wlo[idx] = lo;
        }
    } else if (b < 512) {
        int t = b - 256;
        do_transpose(w_ih, g_wT_ih, GATES, HID, t & 7, t >> 3, tid);
    } else if (b < 528) {
        int t = b - 512;
        do_transpose(fc_w, g_fcwT, HID, LATENT, t & 1, t >> 1, tid);
    } else {
        int t = b - 528;
        do_transpose(out_w, g_outT, OUTD, HID, t & 7, t >> 3, tid);
    }
}

// ---------------- h0 = z @ fc_w^T + fc_b ----------------
__global__ void h0_kernel(const float* __restrict__ z, const float* __restrict__ fc_b) {
    __shared__ float sh_z[4][LATENT];
    int tid = threadIdx.x;
    int b0 = blockIdx.x * 4;
    {
        int row = tid >> 6, k = tid & 63;
        sh_z[row][k] = z[(b0 + row) * LATENT + k];
    }
    __syncthreads();
    float acc0 = 0.f, acc1 = 0.f, acc2 = 0.f, acc3 = 0.f;
    int j = tid;
#pragma unroll 8
    for (int k = 0; k < LATENT; k++) {
        float w = g_fcwT[k * HID + j];
        acc0 = fmaf(sh_z[0][k], w, acc0);
        acc1 = fmaf(sh_z[1][k], w, acc1);
        acc2 = fmaf(sh_z[2][k], w, acc2);
        acc3 = fmaf(sh_z[3][k], w, acc3);
    }
    float bb = fc_b[j];
    g_h0[(b0 + 0) * HID + j] = acc0 + bb;
    g_h0[(b0 + 1) * HID + j] = acc1 + bb;
    g_h0[(b0 + 2) * HID + j] = acc2 + bb;
    g_h0[(b0 + 3) * HID + j] = acc3 + bb;
}

// ---------------- x_proj = h0 @ w_ih^T + (b_ih + b_hh) ----------------
__global__ void xproj_kernel(const float* __restrict__ b_ih, const float* __restrict__ b_hh) {
    __shared__ float sh_h[32][33];
    __shared__ float sh_w[32][64];
    int tid = threadIdx.x;
    int b0 = blockIdx.x * 32;
    int n0 = blockIdx.y * 64;
    int r  = tid & 31;
    int cg = tid >> 5;
    float acc[8];
#pragma unroll
    for (int i = 0; i < 8; i++) acc[i] = 0.f;

    for (int kc = 0; kc < HID; kc += 32) {
#pragma unroll
        for (int p = 0; p < 4; p++) {
            int e = tid + 256 * p;
            int row = e >> 5, col = e & 31;
            sh_h[row][col] = g_h0[(b0 + row) * HID + kc + col];
        }
#pragma unroll
        for (int p = 0; p < 8; p++) {
            int e = tid + 256 * p;
            int krow = e >> 6, c = e & 63;
            sh_w[krow][c] = g_wT_ih[(kc + krow) * GATES + n0 + c];
        }
        __syncthreads();
#pragma unroll
        for (int kk = 0; kk < 32; kk++) {
            float a = sh_h[r][kk];
            float4 w0 = *reinterpret_cast<const float4*>(&sh_w[kk][cg * 8]);
            float4 w1 = *reinterpret_cast<const float4*>(&sh_w[kk][cg * 8 + 4]);
            acc[0] = fmaf(a, w0.x, acc[0]);
            acc[1] = fmaf(a, w0.y, acc[1]);
            acc[2] = fmaf(a, w0.z, acc[2]);
            acc[3] = fmaf(a, w0.w, acc[3]);
            acc[4] = fmaf(a, w1.x, acc[4]);
            acc[5] = fmaf(a, w1.y, acc[5]);
            acc[6] = fmaf(a, w1.z, acc[6]);
            acc[7] = fmaf(a, w1.w, acc[7]);
        }
        __syncthreads();
    }
#pragma unroll
    for (int i = 0; i < 8; i++) {
        int n = n0 + cg * 8 + i;
        g_xproj[(b0 + r) * GATES + n] = acc[i] + b_ih[n] + b_hh[n];
    }
}

// ---------------- warp-MMA LSTM recurrence: DSMEM push + cluster barrier ----------------
// 16 clusters x 8 CTAs x 256 threads (R11 skeleton). Per step: MMA over the
// parity tile -> gate exchange -> activations -> each thread pushes its 2
// cells (one interleaved hi/lo 8B word) directly into all 8 cluster CTAs'
// other-parity tile via st.shared::cluster -> barrier.cluster (arrive=release
// orders the remote stores; wait=acquire makes peers' pushes visible).
// No global h round-trip, no fences, no mbarriers.
__global__ void __launch_bounds__(NTH, 1) __cluster_dims__(CLUSTER, 1, 1)
lstm_mma_kernel(int t0, int t1) {
    extern __shared__ char smem[];
    const uint32_t sbase = smem_u32(smem);
    float* xp = (float*)(smem + OFF_XP);     // [16][132]
    float* gx = (float*)(smem + OFF_GX);     // [128][18]

    const int tid  = threadIdx.x;
    const int wid  = tid >> 5;
    const int lane = tid & 31;
    const int rank = blockIdx.x & (CLUSTER - 1);
    const int cl   = blockIdx.x / CLUSTER;
    const int b0   = cl * ROWS;
    const int j0   = rank * JLOC;

    const int gid = lane >> 2;
    const int kl  = (lane & 3) * 2;

    // ---- W fragments into registers (once per chunk) ----
    uint32_t wHi[16][4], wLo[16][4];
    {
        const __nv_bfloat16* Wh = g_whi + rank * 32768;
        const __nv_bfloat16* Wl = g_wlo + rank * 32768;
        const int m0 = wid * 16;
#pragma unroll
        for (int kt = 0; kt < 16; kt++) {
            int k0 = kt * 16 + kl;
            wHi[kt][0] = *(const uint32_t*)&Wh[(m0 + gid) * 256 + k0];
            wHi[kt][1] = *(const uint32_t*)&Wh[(m0 + gid + 8) * 256 + k0];
            wHi[kt][2] = *(const uint32_t*)&Wh[(m0 + gid) * 256 + k0 + 8];
            wHi[kt][3] = *(const uint32_t*)&Wh[(m0 + gid + 8) * 256 + k0 + 8];
            wLo[kt][0] = *(const uint32_t*)&Wl[(m0 + gid) * 256 + k0];
            wLo[kt][1] = *(const uint32_t*)&Wl[(m0 + gid + 8) * 256 + k0];
            wLo[kt][2] = *(const uint32_t*)&Wl[(m0 + gid) * 256 + k0 + 8];
            wLo[kt][3] = *(const uint32_t*)&Wl[(m0 + gid + 8) * 256 + k0 + 8];
        }
    }
    // ---- x_proj slice ----
    for (int idx = tid; idx < ROWS * 128; idx += NTH) {
        int r = idx >> 7, nl = idx & 127;
        int g = nl >> 5, jj = nl & 31;
        xp[r * 132 + nl] = g_xproj[(b0 + r) * GATES + g * HID + j0 + jj];
    }

    // ---- prologue: stage h(t0-1) into buffer t0&1 (full 16 rows, local) ----
    {
        const float* hin = t0 ? (g_hs + (size_t)(t0 - 1) * BATCH * HID) : g_h0;
        char* tb = smem + OFF_SB + (t0 & 1) * BUFSZ;
        for (int i = tid; i < ROWS * 32; i += NTH) {   // 2 iters: 8 cols each
            int row = i >> 5, cb = i & 31;
            const float4* p = (const float4*)(hin + (size_t)(b0 + row) * HID) + cb * 2;
            sts_conv8(tb, row, cb, p[0], p[1]);
        }
    }
    __syncthreads();

    // activation cells: thread -> (ab, aj0), (ab, aj0+1)
    const int ab  = tid >> 4;
    const int aj0 = (tid & 15) * 2;
    float cA, cB;
    if (t0 == 0) { cA = 0.f; cB = 0.f; }
    else {
        float2 cv = *(const float2*)(g_c + (b0 + ab) * HID + j0 + aj0);
        cA = cv.x; cB = cv.y;
    }
    // push destination offset (same in every CTA): row ab, k-pair (j0+aj0)/2
    const uint32_t push_off = (uint32_t)(OFF_SB + ab * ROWSTR + (j0 + aj0) * 4);

    const int n0 = gid, n1 = gid + 8;

    for (int t = t0; t < t1; t++) {
        const char* tb = smem + OFF_SB + (t & 1) * BUFSZ;

        // ---- MMA: 16 kt x 2 n-tiles x 3 products, 6 independent chains ----
        float hh0[4] = {0, 0, 0, 0}, hl0[4] = {0, 0, 0, 0}, lh0[4] = {0, 0, 0, 0};
        float hh1[4] = {0, 0, 0, 0}, hl1[4] = {0, 0, 0, 0}, lh1[4] = {0, 0, 0, 0};
#pragma unroll
        for (int kt = 0; kt < 16; kt++) {
            int kc = kt * 16 + kl;
            // interleaved tile: k-pair p at p*8; hi at +0, lo at +4
            const char* r0p = tb + n0 * ROWSTR + kc * 4;
            uint32_t b0hi = *(const uint32_t*)(r0p);
            uint32_t b0lo = *(const uint32_t*)(r0p + 4);
            uint32_t b1hi = *(const uint32_t*)(r0p + 32);
            uint32_t b1lo = *(const uint32_t*)(r0p + 36);
            mma_bf16(hh0, wHi[kt], b0hi, b1hi);
            mma_bf16(hl0, wHi[kt], b0lo, b1lo);
            mma_bf16(lh0, wLo[kt], b0hi, b1hi);
            const char* r1p = tb + n1 * ROWSTR + kc * 4;
            uint32_t c0hi = *(const uint32_t*)(r1p);
            uint32_t c0lo = *(const uint32_t*)(r1p + 4);
            uint32_t c1hi = *(const uint32_t*)(r1p + 32);
            uint32_t c1lo = *(const uint32_t*)(r1p + 36);
            mma_bf16(hh1, wHi[kt], c0hi, c1hi);
            mma_bf16(hl1, wHi[kt], c0lo, c1lo);
            mma_bf16(lh1, wLo[kt], c0hi, c1hi);
        }

        // ---- gate exchange: gx[nl][b] ----
        {
            const int nl0 = wid * 16 + gid;
            const int bc  = 2 * (lane & 3);
            *(float2*)&gx[nl0 * 18 + bc] =
                make_float2(hh0[0] + hl0[0] + lh0[0], hh0[1] + hl0[1] + lh0[1]);
            *(float2*)&gx[(nl0 + 8) * 18 + bc] =
                make_float2(hh0[2] + hl0[2] + lh0[2], hh0[3] + hl0[3] + lh0[3]);
            *(float2*)&gx[nl0 * 18 + bc + 8] =
                make_float2(hh1[0] + hl1[0] + lh1[0], hh1[1] + hl1[1] + lh1[1]);
            *(float2*)&gx[(nl0 + 8) * 18 + bc + 8] =
                make_float2(hh1[2] + hl1[2] + lh1[2], hh1[3] + hl1[3] + lh1[3]);
        }
        __syncthreads();

        // ---- fused activations (2 cells/thread) + STG + direct DSMEM push ----
        {
            int aj1 = aj0 + 1;
            float gi0 = gx[aj0 * 18 + ab]        + xp[ab * 132 + aj0];
            float gf0 = gx[(32 + aj0) * 18 + ab] + xp[ab * 132 + 32 + aj0];
            float gg0 = gx[(64 + aj0) * 18 + ab] + xp[ab * 132 + 64 + aj0];
            float go0 = gx[(96 + aj0) * 18 + ab] + xp[ab * 132 + 96 + aj0];
            float gi1 = gx[aj1 * 18 + ab]        + xp[ab * 132 + aj1];
            float gf1 = gx[(32 + aj1) * 18 + ab] + xp[ab * 132 + 32 + aj1];
            float gg1 = gx[(64 + aj1) * 18 + ab] + xp[ab * 132 + 64 + aj1];
            float go1 = gx[(96 + aj1) * 18 + ab] + xp[ab * 132 + 96 + aj1];

            cA = sigmoid_x(gf0) * cA + sigmoid_x(gi0) * tanh_x(gg0);
            float hA = sigmoid_x(go0) * tanh_x(cA);
            cB = sigmoid_x(gf1) * cB + sigmoid_x(gi1) * tanh_x(gg1);
            float hB = sigmoid_x(go1) * tanh_x(cB);

            // fp32 h for the output projection (consumed after kernel boundary)
            *(float2*)(g_hs + (size_t)t * BATCH * HID
                       + (size_t)(b0 + ab) * HID + j0 + aj0) = make_float2(hA, hB);

            if (t < t1 - 1) {
                // pack [hi pair | lo pair] into one 8B word
                __nv_bfloat16 hiA = __float2bfloat16(hA);
                __nv_bfloat16 loA = __float2bfloat16(hA - __bfloat162float(hiA));
                __nv_bfloat16 hiB = __float2bfloat16(hB);
                __nv_bfloat16 loB = __float2bfloat16(hB - __bfloat162float(hiB));
                uint32_t hi2, lo2;
                *(__nv_bfloat162*)&hi2 = __halves2bfloat162(hiA, hiB);
                *(__nv_bfloat162*)&lo2 = __halves2bfloat162(loA, loB);
                unsigned long long v64 =
                    ((unsigned long long)lo2 << 32) | (unsigned long long)hi2;
                uint32_t laddr = sbase + push_off + (uint32_t)(((t + 1) & 1) * BUFSZ);
#pragma unroll
                for (int r = 0; r < CLUSTER; r++) {
                    uint32_t ra = mapa_u32(laddr, (uint32_t)r);
                    asm volatile("st.shared::cluster.b64 [%0], %1;"
                                 :: "r"(ra), "l"(v64) : "memory");
                }
            }
        }

        // ---- step barrier: release our pushes, acquire peers' ----
        if (t < t1 - 1) {
            asm volatile("barrier.cluster.arrive.aligned;" ::: "memory");
            asm volatile("barrier.cluster.wait.aligned;" ::: "memory");
        }
    }

    // spill c-state
    *(float2*)(g_c + (b0 + ab) * HID + j0 + aj0) = make_float2(cA, cB);
}

// ---------------- output projection (f32x2) ----------------
__global__ void out_kernel(const float* __restrict__ out_b, float* __restrict__ out) {
    __shared__ float2 sh_a2[64][17];
    __shared__ float  sh_w[16][128];
    int tid = threadIdx.x;
    int r0 = blockIdx.x * 64;
    int rr = tid & 15;
    int cg = tid >> 4;

    unsigned long long acc[4][4];
#pragma unroll
    for (int q = 0; q < 4; q++)
#pragma unroll
        for (int i = 0; i < 4; i++) acc[q][i] = 0ull;

    for (int kc = 0; kc < HID; kc += 16) {
#pragma unroll
        for (int p = 0; p < 4; p++) {
            int e = tid + 256 * p;
            int row = e >> 4, kk = e & 15;
            float v = g_hs[(size_t)(r0 + row) * HID + kc + kk];
            sh_a2[row][kk] = make_float2(v, v);
        }
#pragma unroll
        for (int p = 0; p < 8; p++) {
            int e = tid + 256 * p;
            int krow = e >> 7, c = e & 127;
            int c8 = c >> 3, i = c & 7;
            sh_w[krow][(i >> 2) * 64 + c8 * 4 + (i & 3)] = g_outT[(kc + krow) * OUTD + c];
        }
        __syncthreads();
#pragma unroll
        for (int kk = 0; kk < 16; kk++) {
            unsigned long long p0 = *(const unsigned long long*)&sh_a2[rr][kk];
            unsigned long long p1 = *(const unsigned long long*)&sh_a2[rr + 16][kk];
            unsigned long long p2 = *(const unsigned long long*)&sh_a2[rr + 32][kk];
            unsigned long long p3 = *(const unsigned long long*)&sh_a2[rr + 48][kk];
            ulonglong2 wA = *(const ulonglong2*)(&sh_w[kk][cg * 4]);
            ulonglong2 wB = *(const ulonglong2*)(&sh_w[kk][64 + cg * 4]);
            fma2(acc[0][0], p0, wA.x); fma2(acc[0][1], p0, wA.y);
            fma2(acc[0][2], p0, wB.x); fma2(acc[0][3], p0, wB.y);
            fma2(acc[1][0], p1, wA.x); fma2(acc[1][1], p1, wA.y);
            fma2(acc[1][2], p1, wB.x); fma2(acc[1][3], p1, wB.y);
            fma2(acc[2][0], p2, wA.x); fma2(acc[2][1], p2, wA.y);
            fma2(acc[2][2], p2, wB.x); fma2(acc[2][3], p2, wB.y);
            fma2(acc[3][0], p3, wA.x); fma2(acc[3][1], p3, wA.y);
            fma2(acc[3][2], p3, wB.x); fma2(acc[3][3], p3, wB.y);
        }
        __syncthreads();
    }

    float ob[8];
#pragma unroll
    for (int i = 0; i < 8; i++) ob[i] = out_b[cg * 8 + i];

#pragma unroll
    for (int q = 0; q < 4; q++) {
        int rIdx = r0 + rr + 16 * q;
        int t = rIdx >> 8;
        int b = rIdx & 255;
        float* dst = out + ((size_t)b * SEQ + t) * OUTD + cg * 8;
#pragma unroll
        for (int i = 0; i < 4; i++) {
            float2 f = upk2(acc[q][i]);
            dst[2 * i]     = f.x + ob[2 * i];
            dst[2 * i + 1] = f.y + ob[2 * i + 1];
        }
    }
}

// ---------------- launch ----------------
extern "C" void kernel_launch(void* const* d_in, const int* in_sizes, int n_in,
                              void* d_out, int out_size) {
    const float* z     = (const float*)d_in[0];
    const float* fc_w  = (const float*)d_in[1];
    const float* fc_b  = (const float*)d_in[2];
    const float* w_ih  = (const float*)d_in[3];
    const float* w_hh  = (const float*)d_in[4];
    const float* b_ih  = (const float*)d_in[5];
    const float* b_hh  = (const float*)d_in[6];
    const float* out_w = (const float*)d_in[7];
    const float* out_b = (const float*)d_in[8];
    float* out = (float*)d_out;

    cudaFuncSetAttribute(lstm_mma_kernel,
                         cudaFuncAttributeMaxDynamicSharedMemorySize, SMEM_LSTM);

    // launch 0: weight prep
    prep_kernel<<<560, 256>>>(w_hh, w_ih, fc_w, out_w);
    // launch 1: h0
    h0_kernel<<<BATCH / 4, 256>>>(z, fc_b);
    // launch 2: x_proj
    xproj_kernel<<<dim3(BATCH / 32, GATES / 64), 256>>>(b_ih, b_hh);
    // launches 3..6: recurrence, 4 chunks of 128 steps
    for (int c = 0; c < SEQ / CHUNK; c++) {
        lstm_mma_kernel<<<NCLUSTER * CLUSTER, NTH, SMEM_LSTM>>>(
            c * CHUNK, (c + 1) * CHUNK);
    }
    // launch 7: output projection
    out_kernel<<<(SEQ * BATCH) / 64, 256>>>(out_b, out);
}